// round 15
// baseline (speedup 1.0000x reference)
#include <cuda_runtime.h>

#define D          1024
#define NHEAD      10004
#define SHORTLIST  10000
#define NPROJ      960
#define NCL        90000
#define NTGT       4096

#define FK_THREADS 512
#define FK_WARPS   16
#define PROJ_BLOCKS 60                                     // 960 rows / 16 warps
#define HEAD_BLOCKS ((NHEAD + FK_WARPS - 1) / FK_WARPS)    // 626 (1 row/warp)
// 2KB chunks, 2 chunks per warp task (R13 sweet spot):
//   seg1 5000, seg2 5000, seg3 5000, seg4 1250 tasks
#define S1_BLOCKS 313     // ceil(5000/16)
#define S2_BLOCKS 313
#define S3_BLOCKS 313
#define S4_BLOCKS 79      // ceil(1250/16)
#define CL_BLOCKS (S1_BLOCKS + S2_BLOCKS + S3_BLOCKS + S4_BLOCKS)  // 1018
#define HEAD_BASE   PROJ_BLOCKS
#define CL_BASE     (PROJ_BLOCKS + HEAD_BLOCKS)
#define NBLOCKS     (PROJ_BLOCKS + HEAD_BLOCKS + CL_BLOCKS)

#define LOSS_THREADS 512

// Scratch (allocation-free __device__ globals; reset by the loss block)
__device__ float g_head_logits[NHEAD];
__device__ float g_proj[NPROJ];
__device__ float g_cl[NCL];       // cluster logits, vocab order (t - 10000)
__device__ float g_sumexp[5];
__device__ int   g_proj_ctr;

__device__ __forceinline__ float warp_sum(float v) {
#pragma unroll
    for (int o = 16; o; o >>= 1) v += __shfl_xor_sync(0xffffffffu, v, o);
    return v;
}
__device__ __forceinline__ float half16_sum(float v) {   // reduce within 16-lane halves
#pragma unroll
    for (int o = 8; o; o >>= 1) v += __shfl_xor_sync(0xffffffffu, v, o);
    return v;
}
__device__ __forceinline__ float dot4(float4 a, float4 b) {
    return a.x * b.x + a.y * b.y + a.z * b.z + a.w * b.w;
}
// streaming (evict-first) float4 load for read-once weight data
__device__ __forceinline__ float4 ldcs4(const float4* p) {
    return __ldcs(p);
}

// ---------------------------------------------------------------------------
// Fused kernel (R13 body, unchanged). Grid = [proj 60 | head 626 | cluster
// 1018] blocks, 512 thr. Cluster warps run the 2KB/MLP=4 body twice
// (sequential, unroll 1). Weights stream with .cs.
// ---------------------------------------------------------------------------
__global__ void __launch_bounds__(FK_THREADS)
fused_kernel(const float* __restrict__ feature,
             const float* __restrict__ head_w,
             const float* __restrict__ t0p, const float* __restrict__ t0w,
             const float* __restrict__ t1p, const float* __restrict__ t1w,
             const float* __restrict__ t2p, const float* __restrict__ t2w,
             const float* __restrict__ t3p, const float* __restrict__ t3w) {
    __shared__ float sv[D];
    __shared__ float s_sum;
    const int tid = threadIdx.x, lane = tid & 31, warp = tid >> 5;
    const int bid = blockIdx.x;

    if (tid == 0) s_sum = 0.f;

    if (bid < PROJ_BLOCKS) {
        // ---------------- proj blocks ----------------
        const int row = bid * FK_WARPS + warp;    // 0..959
        const float* w;
        if      (row < 512) w = t0p + (size_t)row * D;
        else if (row < 768) w = t1p + (size_t)(row - 512) * D;
        else if (row < 896) w = t2p + (size_t)(row - 768) * D;
        else                w = t3p + (size_t)(row - 896) * D;

        const float4* w4 = (const float4*)w;
        const float4* f4 = (const float4*)feature;
        float acc = 0.f;
#pragma unroll
        for (int j = 0; j < 8; j++)
            acc += dot4(ldcs4(&w4[lane + j * 32]), f4[lane + j * 32]);
        acc = warp_sum(acc);
        if (lane == 0) g_proj[row] = acc;
        __syncthreads();
        if (tid == 0) {
            __threadfence();                      // release g_proj
            atomicAdd(&g_proj_ctr, 1);            // RED (return unused)
        }
        return;
    }

    if (bid < CL_BASE) {
        // ---------------- head blocks (1 row/warp) ----------------
        for (int i = tid; i < D; i += FK_THREADS) sv[i] = feature[i];
        __syncthreads();
        int row = (bid - HEAD_BASE) * FK_WARPS + warp;
        if (row < NHEAD) {
            const float4* w4 = (const float4*)(head_w + (size_t)row * D);
            const float4* v4 = (const float4*)sv;
            float acc = 0.f;
#pragma unroll
            for (int j = 0; j < 8; j++)
                acc += dot4(ldcs4(&w4[lane + j * 32]), v4[lane + j * 32]);
            acc = warp_sum(acc);
            if (lane == 0) {
                g_head_logits[row] = acc;
                atomicAdd(&s_sum, __expf(acc));
            }
        }
        __syncthreads();
        if (tid == 0) atomicAdd(&g_sumexp[0], s_sum);
        return;
    }

    // ------- cluster blocks: 2 sequential 2KB chunks per warp (MLP=4) ------
    const int local = bid - CL_BASE;
    int seg, lenf, proj_off, segtasks, task, outbase;
    const float* wmat;
    if (local < S1_BLOCKS) {
        seg = 1; lenf = 512; wmat = t0w; proj_off = 0;   segtasks = 5000;
        task = local * FK_WARPS + warp;                      outbase = 0;
    } else if (local < S1_BLOCKS + S2_BLOCKS) {
        seg = 2; lenf = 256; wmat = t1w; proj_off = 512; segtasks = 5000;
        task = (local - S1_BLOCKS) * FK_WARPS + warp;        outbase = 10000;
    } else if (local < S1_BLOCKS + S2_BLOCKS + S3_BLOCKS) {
        seg = 3; lenf = 128; wmat = t2w; proj_off = 768; segtasks = 5000;
        task = (local - S1_BLOCKS - S2_BLOCKS) * FK_WARPS + warp;  outbase = 30000;
    } else {
        seg = 4; lenf =  64; wmat = t3w; proj_off = 896; segtasks = 1250;
        task = (local - S1_BLOCKS - S2_BLOCKS - S3_BLOCKS) * FK_WARPS + warp;
        outbase = 70000;
    }

    // wait for proj producers (release via fence+ctr; consume via __ldcg/L2)
    if (tid == 0) {
        while (*(volatile int*)&g_proj_ctr < PROJ_BLOCKS) { }
    }
    __syncthreads();
    for (int i = tid; i < lenf; i += FK_THREADS) sv[i] = __ldcg(&g_proj[proj_off + i]);
    __syncthreads();

    if (task < segtasks) {
        const float4* v4 = (const float4*)sv;
        const int vm = (lenf >> 2) - 1;              // power-of-two mask
        float es = 0.f;
#pragma unroll 1
        for (int cc = 0; cc < 2; cc++) {
            const int chunk = task * 2 + cc;         // segment-local 2KB chunk
            const float4* w4 = (const float4*)wmat + (size_t)chunk * 128;
            float4 w0 = ldcs4(&w4[lane]);       float4 w1 = ldcs4(&w4[lane + 32]);
            float4 w2 = ldcs4(&w4[lane + 64]);  float4 w3 = ldcs4(&w4[lane + 96]);
            float a0 = dot4(w0, v4[lane & vm]);
            float a1 = dot4(w1, v4[(lane + 32) & vm]);
            float a2 = dot4(w2, v4[(lane + 64) & vm]);
            float a3 = dot4(w3, v4[(lane + 96) & vm]);

            if (seg == 1) {                       // 1 row/chunk
                float r = warp_sum(a0 + a1 + a2 + a3);
                if (lane == 0) { g_cl[outbase + chunk] = r; es += __expf(r); }
            } else if (seg == 2) {                // 2 rows/chunk
                float r0 = warp_sum(a0 + a1);
                float r1 = warp_sum(a2 + a3);
                if (lane == 0) {
                    *(float2*)&g_cl[outbase + chunk * 2] = make_float2(r0, r1);
                    es += __expf(r0) + __expf(r1);
                }
            } else if (seg == 3) {                // 4 rows/chunk
                float r0 = warp_sum(a0), r1 = warp_sum(a1);
                float r2 = warp_sum(a2), r3 = warp_sum(a3);
                if (lane == 0) {
                    *(float4*)&g_cl[outbase + chunk * 4] = make_float4(r0, r1, r2, r3);
                    es += __expf(r0) + __expf(r1) + __expf(r2) + __expf(r3);
                }
            } else {                              // 8 rows/chunk (16-lane halves)
                float h0 = half16_sum(a0), h1 = half16_sum(a1);
                float h2 = half16_sum(a2), h3 = half16_sum(a3);
                float o0 = __shfl_sync(0xffffffffu, h0, 16);
                float o1 = __shfl_sync(0xffffffffu, h1, 16);
                float o2 = __shfl_sync(0xffffffffu, h2, 16);
                float o3 = __shfl_sync(0xffffffffu, h3, 16);
                if (lane == 0) {
                    float* p = &g_cl[outbase + chunk * 8];
                    *(float4*)p       = make_float4(h0, o0, h1, o1);
                    *(float4*)(p + 4) = make_float4(h2, o2, h3, o3);
                    es += __expf(h0) + __expf(o0) + __expf(h1) + __expf(o1)
                        + __expf(h2) + __expf(o2) + __expf(h3) + __expf(o3);
                }
            }
        }
        if (lane == 0) atomicAdd(&s_sum, es);
    }
    __syncthreads();
    if (tid == 0) atomicAdd(&g_sumexp[seg], s_sum);
}

// ---------------------------------------------------------------------------
// K2: single-block gather-loss with PDL. 512 threads x 8 targets each.
// Pre-sync: targets loaded (2x int4/thread, overlaps fused kernel).
// Post-sync: 8 independent gathers per thread (MLP=8, one L2 round), one
// in-block reduction, direct out[0] store (no atomics, no pre-zeroing).
// Resets scratch for the next graph replay.
// ---------------------------------------------------------------------------
__global__ void __launch_bounds__(LOSS_THREADS)
loss_kernel(const int* __restrict__ targets, float* __restrict__ out) {
    __shared__ float sh[16];
    const int tid = threadIdx.x, lane = tid & 31, warp = tid >> 5;

    // pre-sync: load 8 targets & classify (overlaps fused kernel's drain)
    const int4* t4p = (const int4*)targets;
    int4 ta = t4p[tid];                 // targets[4*tid .. 4*tid+3]
    int4 tb = t4p[tid + LOSS_THREADS];  // second half
    int ts[8] = {ta.x, ta.y, ta.z, ta.w, tb.x, tb.y, tb.z, tb.w};
    int ci[8];
#pragma unroll
    for (int k = 0; k < 8; k++) {
        int t = ts[k];
        if (t < SHORTLIST)       ci[k] = -1;
        else if (t < 20000)      ci[k] = 0;
        else if (t < 40000)      ci[k] = 1;
        else if (t < 80000)      ci[k] = 2;
        else                     ci[k] = 3;
    }

    cudaGridDependencySynchronize();   // wait for fused_kernel (PDL)

    // lse values: cheap, computed per-thread from L2
    float lse[5];
#pragma unroll
    for (int s = 0; s < 5; s++) lse[s] = logf(__ldcg(&g_sumexp[s]));

    float local = 0.f;
#pragma unroll
    for (int k = 0; k < 8; k++) {
        int t = ts[k];
        float lp;
        if (ci[k] < 0) {
            lp = __ldcg(&g_head_logits[t]) - lse[0];
        } else {
            lp = __ldcg(&g_cl[t - SHORTLIST]) - lse[1 + ci[k]]
               + __ldcg(&g_head_logits[SHORTLIST + ci[k]]) - lse[0];
        }
        local += lp;
    }
    local = warp_sum(local);
    if (lane == 0) sh[warp] = local;
    __syncthreads();
    if (warp == 0) {
        float v = (lane < 16) ? sh[lane] : 0.f;
        v = warp_sum(v);
        if (lane == 0) out[0] = -v / (float)NTGT;
    }

    // reset scratch for the next graph replay (deterministic)
    __syncthreads();
    if (tid == 0) g_proj_ctr = 0;
    if (tid < 5)  g_sumexp[tid] = 0.f;
}

// ---------------------------------------------------------------------------
extern "C" void kernel_launch(void* const* d_in, const int* in_sizes, int n_in,
                              void* d_out, int out_size) {
    const float* feature = (const float*)d_in[0];
    const int*   targets = (const int*)  d_in[1];
    const float* head_w  = (const float*)d_in[2];
    const float* t0p     = (const float*)d_in[3];
    const float* t0w     = (const float*)d_in[4];
    const float* t1p     = (const float*)d_in[5];
    const float* t1w     = (const float*)d_in[6];
    const float* t2p     = (const float*)d_in[7];
    const float* t2w     = (const float*)d_in[8];
    const float* t3p     = (const float*)d_in[9];
    const float* t3w     = (const float*)d_in[10];

    fused_kernel<<<NBLOCKS, FK_THREADS>>>(feature, head_w,
                                          t0p, t0w, t1p, t1w,
                                          t2p, t2w, t3p, t3w);

    // PDL launch: overlap loss_kernel's launch + pre-sync work with fused_kernel.
    cudaLaunchConfig_t cfg = {};
    cfg.gridDim  = dim3(1, 1, 1);
    cfg.blockDim = dim3(LOSS_THREADS, 1, 1);
    cfg.dynamicSmemBytes = 0;
    cfg.stream = 0;   // legacy default stream (same as <<<>>> above)
    cudaLaunchAttribute attrs[1];
    attrs[0].id = cudaLaunchAttributeProgrammaticStreamSerialization;
    attrs[0].val.programmaticStreamSerializationAllowed = 1;
    cfg.attrs = attrs;
    cfg.numAttrs = 1;
    cudaLaunchKernelEx(&cfg, loss_kernel, targets, (float*)d_out);
}

// round 16
// speedup vs baseline: 1.3367x; 1.3367x over previous
#include <cuda_runtime.h>

#define D          1024
#define NHEAD      10004
#define SHORTLIST  10000
#define NPROJ      960
#define NCL        90000
#define NTGT       4096

#define FK_THREADS 512
#define FK_WARPS   16
#define PROJ_BLOCKS 60                                     // 960 rows / 16 warps
#define HEAD_BLOCKS ((NHEAD + FK_WARPS - 1) / FK_WARPS)    // 626 (1 row/warp)
// 2KB chunks, 2 chunks per warp task (R13 sweet spot):
//   seg1 5000, seg2 5000, seg3 5000, seg4 1250 tasks
#define S1_BLOCKS 313     // ceil(5000/16)
#define S2_BLOCKS 313
#define S3_BLOCKS 313
#define S4_BLOCKS 79      // ceil(1250/16)
#define CL_BLOCKS (S1_BLOCKS + S2_BLOCKS + S3_BLOCKS + S4_BLOCKS)  // 1018
#define HEAD_BASE   PROJ_BLOCKS
#define CL_BASE     (PROJ_BLOCKS + HEAD_BLOCKS)
#define NBLOCKS     (PROJ_BLOCKS + HEAD_BLOCKS + CL_BLOCKS)

#define LOSS_BLOCKS 64
#define LOSS_THREADS 64

// Scratch (allocation-free __device__ globals; reset by last loss block)
__device__ float g_head_logits[NHEAD];
__device__ float g_proj[NPROJ];
__device__ float g_cl[NCL];       // cluster logits, vocab order (t - 10000)
__device__ float g_sumexp[5];
__device__ int   g_proj_ctr;
__device__ int   g_loss_done;

__device__ __forceinline__ float warp_sum(float v) {
#pragma unroll
    for (int o = 16; o; o >>= 1) v += __shfl_xor_sync(0xffffffffu, v, o);
    return v;
}
__device__ __forceinline__ float half16_sum(float v) {   // reduce within 16-lane halves
#pragma unroll
    for (int o = 8; o; o >>= 1) v += __shfl_xor_sync(0xffffffffu, v, o);
    return v;
}
__device__ __forceinline__ float dot4(float4 a, float4 b) {
    return a.x * b.x + a.y * b.y + a.z * b.z + a.w * b.w;
}
// streaming (evict-first) float4 load for read-once weight data
__device__ __forceinline__ float4 ldcs4(const float4* p) {
    return __ldcs(p);
}

// ---------------------------------------------------------------------------
// Fused kernel (R13 body, byte-identical). Grid = [proj 60 | head 626 |
// cluster 1018] blocks, 512 thr. Cluster warps run the 2KB/MLP=4 body twice
// (sequential, unroll 1). Weights stream with .cs. Block 0 zeroes out[0].
// ---------------------------------------------------------------------------
__global__ void __launch_bounds__(FK_THREADS)
fused_kernel(const float* __restrict__ feature,
             const float* __restrict__ head_w,
             const float* __restrict__ t0p, const float* __restrict__ t0w,
             const float* __restrict__ t1p, const float* __restrict__ t1w,
             const float* __restrict__ t2p, const float* __restrict__ t2w,
             const float* __restrict__ t3p, const float* __restrict__ t3w,
             float* __restrict__ out) {
    __shared__ float sv[D];
    __shared__ float s_sum;
    const int tid = threadIdx.x, lane = tid & 31, warp = tid >> 5;
    const int bid = blockIdx.x;

    if (tid == 0) s_sum = 0.f;

    if (bid < PROJ_BLOCKS) {
        // ---------------- proj blocks ----------------
        if (bid == 0 && tid == 0) out[0] = 0.f;
        const int row = bid * FK_WARPS + warp;    // 0..959
        const float* w;
        if      (row < 512) w = t0p + (size_t)row * D;
        else if (row < 768) w = t1p + (size_t)(row - 512) * D;
        else if (row < 896) w = t2p + (size_t)(row - 768) * D;
        else                w = t3p + (size_t)(row - 896) * D;

        const float4* w4 = (const float4*)w;
        const float4* f4 = (const float4*)feature;
        float acc = 0.f;
#pragma unroll
        for (int j = 0; j < 8; j++)
            acc += dot4(ldcs4(&w4[lane + j * 32]), f4[lane + j * 32]);
        acc = warp_sum(acc);
        if (lane == 0) g_proj[row] = acc;
        __syncthreads();
        if (tid == 0) {
            __threadfence();                      // release g_proj
            atomicAdd(&g_proj_ctr, 1);            // RED (return unused)
        }
        return;
    }

    if (bid < CL_BASE) {
        // ---------------- head blocks (1 row/warp) ----------------
        for (int i = tid; i < D; i += FK_THREADS) sv[i] = feature[i];
        __syncthreads();
        int row = (bid - HEAD_BASE) * FK_WARPS + warp;
        if (row < NHEAD) {
            const float4* w4 = (const float4*)(head_w + (size_t)row * D);
            const float4* v4 = (const float4*)sv;
            float acc = 0.f;
#pragma unroll
            for (int j = 0; j < 8; j++)
                acc += dot4(ldcs4(&w4[lane + j * 32]), v4[lane + j * 32]);
            acc = warp_sum(acc);
            if (lane == 0) {
                g_head_logits[row] = acc;
                atomicAdd(&s_sum, __expf(acc));
            }
        }
        __syncthreads();
        if (tid == 0) atomicAdd(&g_sumexp[0], s_sum);
        return;
    }

    // ------- cluster blocks: 2 sequential 2KB chunks per warp (MLP=4) ------
    const int local = bid - CL_BASE;
    int seg, lenf, proj_off, segtasks, task, outbase;
    const float* wmat;
    if (local < S1_BLOCKS) {
        seg = 1; lenf = 512; wmat = t0w; proj_off = 0;   segtasks = 5000;
        task = local * FK_WARPS + warp;                      outbase = 0;
    } else if (local < S1_BLOCKS + S2_BLOCKS) {
        seg = 2; lenf = 256; wmat = t1w; proj_off = 512; segtasks = 5000;
        task = (local - S1_BLOCKS) * FK_WARPS + warp;        outbase = 10000;
    } else if (local < S1_BLOCKS + S2_BLOCKS + S3_BLOCKS) {
        seg = 3; lenf = 128; wmat = t2w; proj_off = 768; segtasks = 5000;
        task = (local - S1_BLOCKS - S2_BLOCKS) * FK_WARPS + warp;  outbase = 30000;
    } else {
        seg = 4; lenf =  64; wmat = t3w; proj_off = 896; segtasks = 1250;
        task = (local - S1_BLOCKS - S2_BLOCKS - S3_BLOCKS) * FK_WARPS + warp;
        outbase = 70000;
    }

    // wait for proj producers (release via fence+ctr; consume via __ldcg/L2)
    if (tid == 0) {
        while (*(volatile int*)&g_proj_ctr < PROJ_BLOCKS) { }
    }
    __syncthreads();
    for (int i = tid; i < lenf; i += FK_THREADS) sv[i] = __ldcg(&g_proj[proj_off + i]);
    __syncthreads();

    if (task < segtasks) {
        const float4* v4 = (const float4*)sv;
        const int vm = (lenf >> 2) - 1;              // power-of-two mask
        float es = 0.f;
#pragma unroll 1
        for (int cc = 0; cc < 2; cc++) {
            const int chunk = task * 2 + cc;         // segment-local 2KB chunk
            const float4* w4 = (const float4*)wmat + (size_t)chunk * 128;
            float4 w0 = ldcs4(&w4[lane]);       float4 w1 = ldcs4(&w4[lane + 32]);
            float4 w2 = ldcs4(&w4[lane + 64]);  float4 w3 = ldcs4(&w4[lane + 96]);
            float a0 = dot4(w0, v4[lane & vm]);
            float a1 = dot4(w1, v4[(lane + 32) & vm]);
            float a2 = dot4(w2, v4[(lane + 64) & vm]);
            float a3 = dot4(w3, v4[(lane + 96) & vm]);

            if (seg == 1) {                       // 1 row/chunk
                float r = warp_sum(a0 + a1 + a2 + a3);
                if (lane == 0) { g_cl[outbase + chunk] = r; es += __expf(r); }
            } else if (seg == 2) {                // 2 rows/chunk
                float r0 = warp_sum(a0 + a1);
                float r1 = warp_sum(a2 + a3);
                if (lane == 0) {
                    *(float2*)&g_cl[outbase + chunk * 2] = make_float2(r0, r1);
                    es += __expf(r0) + __expf(r1);
                }
            } else if (seg == 3) {                // 4 rows/chunk
                float r0 = warp_sum(a0), r1 = warp_sum(a1);
                float r2 = warp_sum(a2), r3 = warp_sum(a3);
                if (lane == 0) {
                    *(float4*)&g_cl[outbase + chunk * 4] = make_float4(r0, r1, r2, r3);
                    es += __expf(r0) + __expf(r1) + __expf(r2) + __expf(r3);
                }
            } else {                              // 8 rows/chunk (16-lane halves)
                float h0 = half16_sum(a0), h1 = half16_sum(a1);
                float h2 = half16_sum(a2), h3 = half16_sum(a3);
                float o0 = __shfl_sync(0xffffffffu, h0, 16);
                float o1 = __shfl_sync(0xffffffffu, h1, 16);
                float o2 = __shfl_sync(0xffffffffu, h2, 16);
                float o3 = __shfl_sync(0xffffffffu, h3, 16);
                if (lane == 0) {
                    float* p = &g_cl[outbase + chunk * 8];
                    *(float4*)p       = make_float4(h0, o0, h1, o1);
                    *(float4*)(p + 4) = make_float4(h2, o2, h3, o3);
                    es += __expf(h0) + __expf(o0) + __expf(h1) + __expf(o1)
                        + __expf(h2) + __expf(o2) + __expf(h3) + __expf(o3);
                }
            }
        }
        if (lane == 0) atomicAdd(&s_sum, es);
    }
    __syncthreads();
    if (tid == 0) atomicAdd(&g_sumexp[seg], s_sum);
}

// ---------------------------------------------------------------------------
// K2: gather-loss with PDL. 64 blocks x 64 threads = one target per thread,
// spread across 64 SMs (halved per-SM L1tex queue vs 32 blocks). Targets
// loaded pre-sync; post-sync loads independent. Last block resets scratch.
// ---------------------------------------------------------------------------
__global__ void __launch_bounds__(LOSS_THREADS)
loss_kernel(const int* __restrict__ targets, float* __restrict__ out) {
    __shared__ float sh[2];
    const int tid = threadIdx.x, lane = tid & 31, warp = tid >> 5;

    // pre-sync: load target & classify (overlaps fused kernel's drain)
    const int t = targets[blockIdx.x * LOSS_THREADS + tid];
    int ci = -1;
    if (t >= SHORTLIST) {
        if      (t < 20000) ci = 0;
        else if (t < 40000) ci = 1;
        else if (t < 80000) ci = 2;
        else                ci = 3;
    }

    cudaGridDependencySynchronize();   // wait for fused_kernel (PDL)

    float lp;
    if (ci < 0) {
        float logit = __ldcg(&g_head_logits[t]);
        float se_h  = __ldcg(&g_sumexp[0]);
        lp = logit - logf(se_h);
    } else {
        float logit = __ldcg(&g_cl[t - SHORTLIST]);
        float gate  = __ldcg(&g_head_logits[SHORTLIST + ci]);
        float se_h  = __ldcg(&g_sumexp[0]);
        float se_c  = __ldcg(&g_sumexp[1 + ci]);
        lp = logit + gate - logf(se_h) - logf(se_c);
    }

    float local = warp_sum(lp);
    if (lane == 0) sh[warp] = local;
    __syncthreads();
    if (tid == 0) {
        float v = sh[0] + sh[1];
        atomicAdd(out, -v * (1.0f / NTGT));
        int old = atomicAdd(&g_loss_done, 1);
        if (old == LOSS_BLOCKS - 1) {
            g_loss_done = 0;
            g_proj_ctr  = 0;
            g_sumexp[0] = 0.f; g_sumexp[1] = 0.f; g_sumexp[2] = 0.f;
            g_sumexp[3] = 0.f; g_sumexp[4] = 0.f;
        }
    }
}

// ---------------------------------------------------------------------------
extern "C" void kernel_launch(void* const* d_in, const int* in_sizes, int n_in,
                              void* d_out, int out_size) {
    const float* feature = (const float*)d_in[0];
    const int*   targets = (const int*)  d_in[1];
    const float* head_w  = (const float*)d_in[2];
    const float* t0p     = (const float*)d_in[3];
    const float* t0w     = (const float*)d_in[4];
    const float* t1p     = (const float*)d_in[5];
    const float* t1w     = (const float*)d_in[6];
    const float* t2p     = (const float*)d_in[7];
    const float* t2w     = (const float*)d_in[8];
    const float* t3p     = (const float*)d_in[9];
    const float* t3w     = (const float*)d_in[10];

    fused_kernel<<<NBLOCKS, FK_THREADS>>>(feature, head_w,
                                          t0p, t0w, t1p, t1w,
                                          t2p, t2w, t3p, t3w,
                                          (float*)d_out);

    // PDL launch: overlap loss_kernel's launch + pre-sync work with fused_kernel.
    cudaLaunchConfig_t cfg = {};
    cfg.gridDim  = dim3(LOSS_BLOCKS, 1, 1);
    cfg.blockDim = dim3(LOSS_THREADS, 1, 1);
    cfg.dynamicSmemBytes = 0;
    cfg.stream = 0;   // legacy default stream (same as <<<>>> above)
    cudaLaunchAttribute attrs[1];
    attrs[0].id = cudaLaunchAttributeProgrammaticStreamSerialization;
    attrs[0].val.programmaticStreamSerializationAllowed = 1;
    cfg.attrs = attrs;
    cfg.numAttrs = 1;
    cudaLaunchKernelEx(&cfg, loss_kernel, targets, (float*)d_out);
}